// round 14
// baseline (speedup 1.0000x reference)
#include <cuda_runtime.h>

// out[b,c,d] = 0.5 * sum_p W[z(b),c,p] * t[p,b,c,d]   (z(b) = one-hot argmax)
//   t:  [P=4, B, C=256, L=3] fp32   na: [B, Z=64] fp32   W: [Z=64, C=256, P=4]
//   out:[B, C=256, L=3]
//
// FINAL — converged at the memory-system ceiling (5 benches of this exact
// source: 110.98 / 112.00 / 111.33 / 111.07 / 111.07 us; sigma ~0.4us).
// 781 MB provably-minimal traffic at 7.05 TB/s sustained = the B300-measured
// path-independent LTS chip cap for a mixed R/W stream; traffic/bandwidth =
// 111 us = measured. Design, each point validated by a counter-experiment:
//   - 1 node per 192-thread CTA, grid = B = 50000 (R2/R6/R7 decompositions
//     all regressed via occupancy or loop serialization)
//   - 32 regs, no smem, no barriers -> 86-88% occupancy
//   - per-warp one-hot resolve: one float2 LDG + ballot + shfl, issued FIRST
//     (head of the only dependency chain: na -> ballot -> W -> FMA -> store)
//   - 4 independent float4 t-plane loads issued immediately after, filling
//     the DRAM pipe while the routing index resolves (R4's confirmed win)
//   - default cache policy (ld.cs hurt steady state R3; st.cs neutral R9)
//   - W rows (64 x 4KB) L2/L1-resident, reused 50000x

#define Z_DIM 64
#define C_DIM 256
#define P_DIM 4
#define L_DIM 3
#define CL    (C_DIM * L_DIM)   // 768 floats per (p,b) plane / out row
#define CP    (C_DIM * P_DIM)   // 1024 floats per W[z] row
#define NTHR  (CL / 4)          // 192 threads: one float4 per thread

__global__ void __launch_bounds__(NTHR)
ecwl_kernel(const float* __restrict__ t,
            const float* __restrict__ na,
            const float* __restrict__ W,
            float*       __restrict__ out,
            int B)
{
    const int b    = blockIdx.x;
    const int tid  = threadIdx.x;
    const int lane = tid & 31;
    const int e0   = tid * 4;

    // 1) Head of the dependency chain first: the one-hot row, one float2 per
    //    lane (fully coalesced 256B). Each warp resolves independently.
    const float2 x = __ldg(reinterpret_cast<const float2*>(na + (size_t)b * Z_DIM) + lane);

    // 2) Independent t-plane loads fill the DRAM pipe while na resolves.
    float4 v[P_DIM];
    #pragma unroll
    for (int p = 0; p < P_DIM; ++p)
        v[p] = *reinterpret_cast<const float4*>(
            t + ((size_t)p * B + b) * CL + e0);

    // 3) Ballot routing resolve: hot lane holds the pair (2z, 2z+1).
    const unsigned m = __ballot_sync(0xFFFFFFFFu, (x.x > 0.5f) | (x.y > 0.5f));
    const int hot    = __ffs(m) - 1;
    const float xy   = __shfl_sync(0xFFFFFFFFu, x.y, hot);
    const int zi     = 2 * hot + (xy > 0.5f);

    // 4) Weight row (L1/L2-hot: 64 rows, reused 50000x). float4 = the 4
    //    path-weights of one channel; a thread's t-float4 straddles <=2
    //    channels (L=3).
    const int c0 = e0 / 3;
    const float4* Wr = reinterpret_cast<const float4*>(W + (size_t)zi * CP);
    const float4 w0 = __ldg(Wr + c0);
    const float4 w1 = __ldg(Wr + c0 + 1);   // c0 <= 254, in-bounds

    const float wA[4] = {w0.x, w0.y, w0.z, w0.w};
    const float wB[4] = {w1.x, w1.y, w1.z, w1.w};

    const bool s1 = ((e0 + 1) / 3 == c0);
    const bool s2 = ((e0 + 2) / 3 == c0);
    const bool s3 = ((e0 + 3) / 3 == c0);

    float a0 = 0.f, a1 = 0.f, a2 = 0.f, a3 = 0.f;
    #pragma unroll
    for (int p = 0; p < P_DIM; ++p) {
        const float wa = wA[p], wb = wB[p];
        a0 += wa * v[p].x;
        a1 += (s1 ? wa : wb) * v[p].y;
        a2 += (s2 ? wa : wb) * v[p].z;
        a3 += (s3 ? wa : wb) * v[p].w;
    }

    float4 o = {0.5f * a0, 0.5f * a1, 0.5f * a2, 0.5f * a3};
    reinterpret_cast<float4*>(out)[(size_t)b * NTHR + tid] = o;
}

extern "C" void kernel_launch(void* const* d_in, const int* in_sizes, int n_in,
                              void* d_out, int out_size)
{
    const float* t  = (const float*)d_in[0];   // [P,B,C,L]
    const float* na = (const float*)d_in[1];   // [B,Z]
    const float* W  = (const float*)d_in[2];   // [Z,C,P]
    float* out      = (float*)d_out;           // [B,C,L]

    const int B = in_sizes[1] / Z_DIM;

    ecwl_kernel<<<B, NTHR>>>(t, na, W, out, B);
}